// round 1
// baseline (speedup 1.0000x reference)
#include <cuda_runtime.h>
#include <cuda_bf16.h>
#include <cstdint>

// Problem constants
#define BB 16
#define TT 64
#define SS 256
#define DD 512

// Scratch (device globals — no allocations allowed)
__device__ float g_wq[BB * TT * DD];          // (B,T,D)   2 MB
__device__ float g_uh[BB * SS * DD];          // (B,S,D)   8 MB
__device__ float g_concat[BB * TT * 2 * DD];  // (B,T,2D)  4 MB

// ---------------------------------------------------------------------------
// tanh: 1 - 2/(1+exp(2x)).  Absolute error ~1e-7 (cancellation only hurts
// relative error near 0 where absolute error is what matters for the dot).
// 2 MUFU ops per call (EX2 + RCP).
// ---------------------------------------------------------------------------
__device__ __forceinline__ float fast_tanh(float x) {
    float e = __expf(2.0f * x);
    return 1.0f - __fdividef(2.0f, 1.0f + e);
}

// ---------------------------------------------------------------------------
// Generic C = A * B^T (+bias) tiled GEMM.
//   A: M x K row-major, Bm: N x K row-major, C: M x N
//   OUT_MODE 0: C[m*N+n]
//   OUT_MODE 1: m = b*TT + t; C[(t*BB+b)*N + n]   (for (T,B,D) output)
// BM=BN=64, BK=16, 256 threads, 4x4 per thread.
// Requires M%64==0, N%64==0, K%16==0 (true for all call sites).
// ---------------------------------------------------------------------------
template <int OUT_MODE>
__global__ __launch_bounds__(256)
void gemm_abt(const float* __restrict__ A, const float* __restrict__ Bm,
              const float* __restrict__ bias, float* __restrict__ C,
              int M, int N, int K) {
    __shared__ __align__(16) float As[16][68];
    __shared__ __align__(16) float Bs[16][68];

    const int tid = threadIdx.x;
    const int tx = tid & 15;        // 0..15 -> n sub-tile
    const int ty = tid >> 4;        // 0..15 -> m sub-tile
    const int m0 = blockIdx.y * 64;
    const int n0 = blockIdx.x * 64;

    // loader mapping: each thread loads one float4 from A and one from B
    const int la = tid * 4;
    const int lm = la >> 4;         // row within tile (0..63)
    const int lk = la & 15;         // k within tile (0,4,8,12)

    float acc[4][4];
#pragma unroll
    for (int i = 0; i < 4; i++)
#pragma unroll
        for (int j = 0; j < 4; j++) acc[i][j] = 0.0f;

    for (int k0 = 0; k0 < K; k0 += 16) {
        float4 av = *(const float4*)(A + (size_t)(m0 + lm) * K + k0 + lk);
        float4 bv = *(const float4*)(Bm + (size_t)(n0 + lm) * K + k0 + lk);
        As[lk + 0][lm] = av.x; As[lk + 1][lm] = av.y;
        As[lk + 2][lm] = av.z; As[lk + 3][lm] = av.w;
        Bs[lk + 0][lm] = bv.x; Bs[lk + 1][lm] = bv.y;
        Bs[lk + 2][lm] = bv.z; Bs[lk + 3][lm] = bv.w;
        __syncthreads();

#pragma unroll
        for (int k = 0; k < 16; k++) {
            float4 a = *(const float4*)&As[k][ty * 4];
            float4 b = *(const float4*)&Bs[k][tx * 4];
            float ar[4] = {a.x, a.y, a.z, a.w};
            float br[4] = {b.x, b.y, b.z, b.w};
#pragma unroll
            for (int i = 0; i < 4; i++)
#pragma unroll
                for (int j = 0; j < 4; j++)
                    acc[i][j] = fmaf(ar[i], br[j], acc[i][j]);
        }
        __syncthreads();
    }

#pragma unroll
    for (int i = 0; i < 4; i++) {
        int m = m0 + ty * 4 + i;
#pragma unroll
        for (int j = 0; j < 4; j++) {
            int n = n0 + tx * 4 + j;
            float val = acc[i][j];
            if (bias) val += bias[n];
            if (OUT_MODE == 0) {
                C[(size_t)m * N + n] = val;
            } else {
                int b = m / TT, t = m % TT;
                C[((size_t)t * BB + b) * N + n] = val;
            }
        }
    }
}

// ---------------------------------------------------------------------------
// Per-(b,t) block: align scores, mask, sparsemax, context vector, concat.
// 256 threads (8 warps). Writes sparsemax probs to out_align in (T,B,S)
// layout and [c | source] into g_concat (B,T,2D).
// ---------------------------------------------------------------------------
__global__ __launch_bounds__(256)
void align_sparsemax_kernel(const float* __restrict__ wq,
                            const float* __restrict__ uh,
                            const float* __restrict__ mem,
                            const int* __restrict__ mask,
                            const float* __restrict__ v,
                            const float* __restrict__ src,
                            float* __restrict__ out_align,
                            float* __restrict__ concat) {
    __shared__ float s_wq[DD];
    __shared__ float s_v[DD];
    __shared__ float s_z[SS];   // z = align - max (pre-sort order)
    __shared__ float s_a[SS];   // sorted values, later probs
    __shared__ float s_b[SS];   // cumsum
    __shared__ float s_r[SS];   // reduction scratch

    const int tid = threadIdx.x;
    const int bt = blockIdx.x;
    const int b = bt / TT;
    const int t = bt % TT;

    s_wq[tid]        = wq[(size_t)bt * DD + tid];
    s_wq[tid + 256]  = wq[(size_t)bt * DD + tid + 256];
    s_v[tid]         = v[tid];
    s_v[tid + 256]   = v[tid + 256];
    __syncthreads();

    const int warp = tid >> 5, lane = tid & 31;
    // 8 warps x 32 s-values each
    for (int s = warp; s < SS; s += 8) {
        const float* uhr = uh + ((size_t)b * SS + s) * DD;
        float acc = 0.0f;
#pragma unroll
        for (int i = 0; i < 16; i++) {
            int d = lane + i * 32;
            acc = fmaf(s_v[d], fast_tanh(s_wq[d] + uhr[d]), acc);
        }
#pragma unroll
        for (int off = 16; off; off >>= 1)
            acc += __shfl_xor_sync(0xffffffffu, acc, off);
        if (lane == 0)
            s_z[s] = mask[b * SS + s] ? acc : -1e9f;
    }
    __syncthreads();

    // ---- max reduce ----
    s_r[tid] = s_z[tid];
    __syncthreads();
    for (int st = 128; st; st >>= 1) {
        if (tid < st) s_r[tid] = fmaxf(s_r[tid], s_r[tid + st]);
        __syncthreads();
    }
    const float zmax = s_r[0];
    __syncthreads();

    float zc = s_z[tid] - zmax;
    s_z[tid] = zc;
    s_a[tid] = zc;
    __syncthreads();

    // ---- bitonic sort descending on s_a ----
    for (int k = 2; k <= 256; k <<= 1) {
        for (int j = k >> 1; j; j >>= 1) {
            int ixj = tid ^ j;
            if (ixj > tid) {
                float x = s_a[tid], y = s_a[ixj];
                bool desc = ((tid & k) == 0);
                bool lt = (x < y);
                if (lt == desc) { s_a[tid] = y; s_a[ixj] = x; }
            }
            __syncthreads();
        }
    }

    // ---- inclusive scan (Hillis-Steele) of s_a into s_b ----
    s_b[tid] = s_a[tid];
    __syncthreads();
    for (int off = 1; off < 256; off <<= 1) {
        float val = (tid >= off) ? s_b[tid - off] : 0.0f;
        __syncthreads();
        s_b[tid] += val;
        __syncthreads();
    }

    // ---- support size & tau ----
    float zcum = s_b[tid] - 1.0f;
    float flag = ((float)(tid + 1) * s_a[tid] > zcum) ? 1.0f : 0.0f;
    s_r[tid] = flag;
    __syncthreads();
    for (int st = 128; st; st >>= 1) {
        if (tid < st) s_r[tid] += s_r[tid + st];
        __syncthreads();
    }
    const int supp = (int)s_r[0];
    const float tau = (s_b[supp - 1] - 1.0f) / (float)supp;

    // ---- probabilities ----
    float p = fmaxf(s_z[tid] - tau, 0.0f);
    out_align[((size_t)t * BB + b) * SS + tid] = p;
    __syncthreads();          // ensure sorted s_a reads done before overwrite
    s_a[tid] = p;
    __syncthreads();

    // ---- context vector c (sparse: support is typically tiny) + concat ----
    const int d0 = tid, d1 = tid + 256;
    const float* memb = mem + (size_t)b * SS * DD;
    float c0 = 0.0f, c1 = 0.0f;
    for (int s = 0; s < SS; s++) {
        float ps = s_a[s];
        if (ps != 0.0f) {
            const float* row = memb + (size_t)s * DD;
            c0 = fmaf(ps, row[d0], c0);
            c1 = fmaf(ps, row[d1], c1);
        }
    }
    float* crow = concat + (size_t)bt * (2 * DD);
    const float* srow = src + (size_t)bt * DD;
    crow[d0] = c0;
    crow[d1] = c1;
    crow[DD + d0] = srow[d0];
    crow[DD + d1] = srow[d1];
}

// ---------------------------------------------------------------------------
extern "C" void kernel_launch(void* const* d_in, const int* in_sizes, int n_in,
                              void* d_out, int out_size) {
    const float* source      = (const float*)d_in[0];  // (B,T,D)
    const float* memory_bank = (const float*)d_in[1];  // (B,S,D)
    const int*   memory_mask = (const int*)d_in[2];    // (B,S)
    const float* W_q         = (const float*)d_in[3];  // (D,D)
    const float* b_q         = (const float*)d_in[4];  // (D)
    const float* W_c         = (const float*)d_in[5];  // (D,D)
    const float* v           = (const float*)d_in[6];  // (D)
    const float* W_out       = (const float*)d_in[7];  // (D,2D)
    const float* b_out       = (const float*)d_in[8];  // (D)

    float* out       = (float*)d_out;
    float* out_attn  = out;                       // (T,B,D)
    float* out_align = out + (size_t)TT * BB * DD; // (T,B,S)

    float *p_wq, *p_uh, *p_cc;
    cudaGetSymbolAddress((void**)&p_wq, g_wq);
    cudaGetSymbolAddress((void**)&p_uh, g_uh);
    cudaGetSymbolAddress((void**)&p_cc, g_concat);

    // wq = source @ W_q^T + b_q    (M=1024, N=512, K=512)
    gemm_abt<0><<<dim3(DD / 64, (BB * TT) / 64), 256>>>(
        source, W_q, b_q, p_wq, BB * TT, DD, DD);

    // uh = memory_bank @ W_c^T     (M=4096, N=512, K=512)
    gemm_abt<0><<<dim3(DD / 64, (BB * SS) / 64), 256>>>(
        memory_bank, W_c, nullptr, p_uh, BB * SS, DD, DD);

    // align + sparsemax + context + concat
    align_sparsemax_kernel<<<BB * TT, 256>>>(
        p_wq, p_uh, memory_bank, memory_mask, v, source, out_align, p_cc);

    // attn_h = concat @ W_out^T + b_out, written transposed to (T,B,D)
    gemm_abt<1><<<dim3(DD / 64, (BB * TT) / 64), 256>>>(
        p_cc, W_out, b_out, out_attn, BB * TT, DD, 2 * DD);
}

// round 2
// speedup vs baseline: 1.1001x; 1.1001x over previous
#include <cuda_runtime.h>
#include <cuda_bf16.h>
#include <cstdint>

// Problem constants
#define BB 16
#define TT 64
#define SS 256
#define DD 512
#define SPLITK 4

// Scratch (device globals — no allocations allowed)
__device__ float g_wq[BB * TT * DD];            // (B,T,D)   2 MB
__device__ float g_uh[BB * SS * DD];            // (B,S,D)   8 MB
__device__ float g_concat[BB * TT * 2 * DD];    // (B,T,2D)  4 MB
__device__ float g_part[SPLITK * BB * TT * DD]; // split-K partials 8 MB

// HW tanh (sm_75+): max rel err ~2^-11, single MUFU op.
__device__ __forceinline__ float htanh(float x) {
    float y;
    asm("tanh.approx.f32 %0, %1;" : "=f"(y) : "f"(x));
    return y;
}

// ---------------------------------------------------------------------------
// GEMM core: C = A * B^T, tile BM=128 x BN=64, BK=16, 256 threads,
// thread tile 8x4, register-prefetch double buffering.
//   A: rows at A + (mbase+r)*Kld, r in [0,128)
//   B: rows at Bm + (n0+r)*Kld,   r in [0,64)
//   K range [kbeg, kend) (multiples of 16)
// ---------------------------------------------------------------------------
__device__ __forceinline__ void gemm_core(
    const float* __restrict__ A, const float* __restrict__ Bm,
    const float* __restrict__ bias, float* __restrict__ C,
    int mbase, int n0, int N, int Kld, int kbeg, int kend)
{
    __shared__ __align__(16) float As[16][132];
    __shared__ __align__(16) float Bs[16][68];

    const int tid = threadIdx.x;
    const int tx = tid & 15;   // n sub-tile (4 cols)
    const int ty = tid >> 4;   // m sub-tile (8 rows)

    const int ar0 = tid >> 2;          // A tile row 0..63
    const int ar1 = ar0 + 64;          // A tile row 64..127
    const int ak  = (tid & 3) * 4;     // k offset 0,4,8,12
    const int br  = tid >> 2;          // B tile row 0..63

    const float* Ab = A + (size_t)mbase * Kld;
    const float* Bb = Bm + (size_t)n0 * Kld;

    float4 a0v = *(const float4*)(Ab + (size_t)ar0 * Kld + kbeg + ak);
    float4 a1v = *(const float4*)(Ab + (size_t)ar1 * Kld + kbeg + ak);
    float4 bv  = *(const float4*)(Bb + (size_t)br  * Kld + kbeg + ak);

    float acc[8][4];
#pragma unroll
    for (int i = 0; i < 8; i++)
#pragma unroll
        for (int j = 0; j < 4; j++) acc[i][j] = 0.0f;

    for (int k0 = kbeg; k0 < kend; k0 += 16) {
        As[ak + 0][ar0] = a0v.x; As[ak + 1][ar0] = a0v.y;
        As[ak + 2][ar0] = a0v.z; As[ak + 3][ar0] = a0v.w;
        As[ak + 0][ar1] = a1v.x; As[ak + 1][ar1] = a1v.y;
        As[ak + 2][ar1] = a1v.z; As[ak + 3][ar1] = a1v.w;
        Bs[ak + 0][br]  = bv.x;  Bs[ak + 1][br]  = bv.y;
        Bs[ak + 2][br]  = bv.z;  Bs[ak + 3][br]  = bv.w;
        __syncthreads();

        if (k0 + 16 < kend) {
            a0v = *(const float4*)(Ab + (size_t)ar0 * Kld + k0 + 16 + ak);
            a1v = *(const float4*)(Ab + (size_t)ar1 * Kld + k0 + 16 + ak);
            bv  = *(const float4*)(Bb + (size_t)br  * Kld + k0 + 16 + ak);
        }

#pragma unroll
        for (int k = 0; k < 16; k++) {
            float4 aa0 = *(const float4*)&As[k][ty * 8];
            float4 aa1 = *(const float4*)&As[k][ty * 8 + 4];
            float4 b4  = *(const float4*)&Bs[k][tx * 4];
            float ar[8] = {aa0.x, aa0.y, aa0.z, aa0.w, aa1.x, aa1.y, aa1.z, aa1.w};
            float brr[4] = {b4.x, b4.y, b4.z, b4.w};
#pragma unroll
            for (int i = 0; i < 8; i++)
#pragma unroll
                for (int j = 0; j < 4; j++)
                    acc[i][j] = fmaf(ar[i], brr[j], acc[i][j]);
        }
        __syncthreads();
    }

    // epilogue: one float4 store per output row chunk
    float4 bb = make_float4(0.f, 0.f, 0.f, 0.f);
    if (bias) bb = *(const float4*)(bias + n0 + tx * 4);
#pragma unroll
    for (int i = 0; i < 8; i++) {
        int m = mbase + ty * 8 + i;
        float4 o;
        o.x = acc[i][0] + bb.x; o.y = acc[i][1] + bb.y;
        o.z = acc[i][2] + bb.z; o.w = acc[i][3] + bb.w;
        *(float4*)(C + (size_t)m * N + n0 + tx * 4) = o;
    }
}

// Fused wq + uh GEMM: grid.y tiles 0..7 -> wq (M=1024), 8..39 -> uh (M=4096)
__global__ __launch_bounds__(256)
void gemm_qc(const float* __restrict__ src, const float* __restrict__ mem,
             const float* __restrict__ Wq, const float* __restrict__ bq,
             const float* __restrict__ Wc,
             float* __restrict__ wq_out, float* __restrict__ uh_out) {
    int my = blockIdx.y;
    if (my < 8) {
        gemm_core(src, Wq, bq, wq_out, my * 128, blockIdx.x * 64, DD, DD, 0, DD);
    } else {
        gemm_core(mem, Wc, nullptr, uh_out, (my - 8) * 128, blockIdx.x * 64, DD, DD, 0, DD);
    }
}

// W_out GEMM, split-K=4 into partial buffers
__global__ __launch_bounds__(256)
void gemm_out(const float* __restrict__ cc, const float* __restrict__ Wout,
              float* __restrict__ part) {
    int z = blockIdx.z;
    gemm_core(cc, Wout, nullptr, part + (size_t)z * BB * TT * DD,
              blockIdx.y * 128, blockIdx.x * 64, DD, 2 * DD,
              z * (2 * DD / SPLITK), (z + 1) * (2 * DD / SPLITK));
}

// Reduce split-K partials + bias, write transposed (T,B,D)
__global__ __launch_bounds__(256)
void reduce_out(const float* __restrict__ part, const float* __restrict__ bout,
                float* __restrict__ out) {
    int i = blockIdx.x * 256 + threadIdx.x;     // float4 index, 131072 total
    int e = i * 4;
    int m = e >> 9;          // row 0..1023
    int n = e & 511;
    float4 s = make_float4(0.f, 0.f, 0.f, 0.f);
#pragma unroll
    for (int z = 0; z < SPLITK; z++) {
        float4 p = *(const float4*)(part + (size_t)z * BB * TT * DD + e);
        s.x += p.x; s.y += p.y; s.z += p.z; s.w += p.w;
    }
    float4 bb = *(const float4*)(bout + n);
    s.x += bb.x; s.y += bb.y; s.z += bb.z; s.w += bb.w;
    int b = m >> 6, t = m & 63;
    *(float4*)(out + ((size_t)(t * BB + b) << 9) + n) = s;
}

// ---------------------------------------------------------------------------
// Align + sparsemax + context + concat; 4 t's per block (uh/mem rows reused 4x)
// ---------------------------------------------------------------------------
__global__ __launch_bounds__(256)
void align4_kernel(const float* __restrict__ wq, const float* __restrict__ uh,
                   const float* __restrict__ mem, const int* __restrict__ mask,
                   const float* __restrict__ v, const float* __restrict__ src,
                   float* __restrict__ out_align, float* __restrict__ concat) {
    __shared__ float s_wq[4][DD];
    __shared__ float s_v[DD];
    __shared__ float s_z[4][SS];
    __shared__ float s_p[4][SS];
    __shared__ float s_a[SS], s_b[SS], s_r[SS];

    const int tid = threadIdx.x;
    const int b  = blockIdx.x >> 4;      // TT/4 = 16 groups per b
    const int t0 = (blockIdx.x & 15) * 4;

    for (int i = tid; i < 4 * DD; i += 256) {
        int tt = i >> 9, d = i & 511;
        s_wq[tt][d] = wq[((size_t)(b * TT + t0 + tt)) * DD + d];
    }
    s_v[tid] = v[tid];
    s_v[tid + 256] = v[tid + 256];
    __syncthreads();

    const int warp = tid >> 5, lane = tid & 31;
    for (int s = warp; s < SS; s += 8) {
        const float* uhr = uh + ((size_t)(b * SS + s)) * DD;
        float a0 = 0.f, a1 = 0.f, a2 = 0.f, a3 = 0.f;
#pragma unroll
        for (int i = 0; i < 16; i++) {
            int d = lane + i * 32;
            float u = uhr[d];
            float vv = s_v[d];
            a0 = fmaf(vv, htanh(s_wq[0][d] + u), a0);
            a1 = fmaf(vv, htanh(s_wq[1][d] + u), a1);
            a2 = fmaf(vv, htanh(s_wq[2][d] + u), a2);
            a3 = fmaf(vv, htanh(s_wq[3][d] + u), a3);
        }
#pragma unroll
        for (int off = 16; off; off >>= 1) {
            a0 += __shfl_xor_sync(0xffffffffu, a0, off);
            a1 += __shfl_xor_sync(0xffffffffu, a1, off);
            a2 += __shfl_xor_sync(0xffffffffu, a2, off);
            a3 += __shfl_xor_sync(0xffffffffu, a3, off);
        }
        if (lane == 0) {
            bool mk = mask[b * SS + s] != 0;
            s_z[0][s] = mk ? a0 : -1e9f;
            s_z[1][s] = mk ? a1 : -1e9f;
            s_z[2][s] = mk ? a2 : -1e9f;
            s_z[3][s] = mk ? a3 : -1e9f;
        }
    }
    __syncthreads();

    // sparsemax per t (sequential over 4 rows)
    for (int tt = 0; tt < 4; tt++) {
        // max reduce
        s_r[tid] = s_z[tt][tid];
        __syncthreads();
        for (int st = 128; st; st >>= 1) {
            if (tid < st) s_r[tid] = fmaxf(s_r[tid], s_r[tid + st]);
            __syncthreads();
        }
        const float zmax = s_r[0];
        const float zc = s_z[tt][tid] - zmax;
        s_a[tid] = zc;
        __syncthreads();

        // bitonic sort descending
        for (int k = 2; k <= 256; k <<= 1) {
            for (int j = k >> 1; j; j >>= 1) {
                int ixj = tid ^ j;
                if (ixj > tid) {
                    float x = s_a[tid], y = s_a[ixj];
                    bool desc = ((tid & k) == 0);
                    if ((x < y) == desc) { s_a[tid] = y; s_a[ixj] = x; }
                }
                __syncthreads();
            }
        }

        // inclusive scan
        s_b[tid] = s_a[tid];
        __syncthreads();
        for (int off = 1; off < 256; off <<= 1) {
            float val = (tid >= off) ? s_b[tid - off] : 0.0f;
            __syncthreads();
            s_b[tid] += val;
            __syncthreads();
        }

        // support size & tau
        float zcum = s_b[tid] - 1.0f;
        s_r[tid] = ((float)(tid + 1) * s_a[tid] > zcum) ? 1.0f : 0.0f;
        __syncthreads();
        for (int st = 128; st; st >>= 1) {
            if (tid < st) s_r[tid] += s_r[tid + st];
            __syncthreads();
        }
        const int supp = (int)s_r[0];
        const float tau = (s_b[supp - 1] - 1.0f) / (float)supp;

        float p = fmaxf(zc - tau, 0.0f);
        s_p[tt][tid] = p;
        out_align[((size_t)(t0 + tt) * BB + b) * SS + tid] = p;
        __syncthreads();
    }

    // context vectors (mem rows loaded once for all 4 t's) + concat
    const int d0 = tid, d1 = tid + 256;
    const float* memb = mem + (size_t)b * SS * DD;
    float c00 = 0.f, c01 = 0.f, c10 = 0.f, c11 = 0.f;
    float c20 = 0.f, c21 = 0.f, c30 = 0.f, c31 = 0.f;
    for (int s = 0; s < SS; s++) {
        float p0 = s_p[0][s], p1 = s_p[1][s], p2 = s_p[2][s], p3 = s_p[3][s];
        if (p0 + p1 + p2 + p3 != 0.0f) {
            const float* row = memb + (size_t)s * DD;
            float r0 = row[d0], r1 = row[d1];
            c00 = fmaf(p0, r0, c00); c01 = fmaf(p0, r1, c01);
            c10 = fmaf(p1, r0, c10); c11 = fmaf(p1, r1, c11);
            c20 = fmaf(p2, r0, c20); c21 = fmaf(p2, r1, c21);
            c30 = fmaf(p3, r0, c30); c31 = fmaf(p3, r1, c31);
        }
    }
    float cc0[4] = {c00, c10, c20, c30};
    float cc1[4] = {c01, c11, c21, c31};
#pragma unroll
    for (int tt = 0; tt < 4; tt++) {
        float* crow = concat + (size_t)(b * TT + t0 + tt) * (2 * DD);
        const float* srow = src + (size_t)(b * TT + t0 + tt) * DD;
        crow[d0] = cc0[tt];
        crow[d1] = cc1[tt];
        crow[DD + d0] = srow[d0];
        crow[DD + d1] = srow[d1];
    }
}

// ---------------------------------------------------------------------------
extern "C" void kernel_launch(void* const* d_in, const int* in_sizes, int n_in,
                              void* d_out, int out_size) {
    const float* source      = (const float*)d_in[0];
    const float* memory_bank = (const float*)d_in[1];
    const int*   memory_mask = (const int*)d_in[2];
    const float* W_q         = (const float*)d_in[3];
    const float* b_q         = (const float*)d_in[4];
    const float* W_c         = (const float*)d_in[5];
    const float* v           = (const float*)d_in[6];
    const float* W_out       = (const float*)d_in[7];
    const float* b_out       = (const float*)d_in[8];

    float* out       = (float*)d_out;
    float* out_attn  = out;                         // (T,B,D)
    float* out_align = out + (size_t)TT * BB * DD;  // (T,B,S)

    float *p_wq, *p_uh, *p_cc, *p_part;
    cudaGetSymbolAddress((void**)&p_wq, g_wq);
    cudaGetSymbolAddress((void**)&p_uh, g_uh);
    cudaGetSymbolAddress((void**)&p_cc, g_concat);
    cudaGetSymbolAddress((void**)&p_part, g_part);

    // fused wq & uh GEMMs: 320 blocks
    gemm_qc<<<dim3(DD / 64, 8 + 32), 256>>>(
        source, memory_bank, W_q, b_q, W_c, p_wq, p_uh);

    // align + sparsemax + context + concat: 256 blocks
    align4_kernel<<<BB * (TT / 4), 256>>>(
        p_wq, p_uh, memory_bank, memory_mask, v, source, out_align, p_cc);

    // W_out GEMM split-K: 256 blocks
    gemm_out<<<dim3(DD / 64, (BB * TT) / 128, SPLITK), 256>>>(p_cc, W_out, p_part);

    // reduce partials + bias + transpose: 512 blocks
    reduce_out<<<(BB * TT * DD) / (256 * 4), 256>>>(p_part, b_out, out_attn);
}